// round 13
// baseline (speedup 1.0000x reference)
#include <cuda_runtime.h>
#include <math.h>

#define BATCH  128
#define KK     512
#define NSLQ   16     // 32-row slices for all three streaming flavors
#define SLRQ   32
#define TPB    128    // thread owns 4 columns (float4)

#define LOGK 6.2383246250395077632f   // log(512)

// Scratch (__device__ globals). Fits in L2; streaming input loads use __ldcs
// (evict-first) so these stay resident.
__device__ float g_Ep0[NSLQ * BATCH * KK];   // partial col-sums of exp(Q0) (4 MB)
__device__ float g_Ep1[NSLQ * BATCH * KK];   // partial col-sums of exp(Q1) (4 MB)
__device__ float g_mmp[NSLQ * BATCH * KK];   // partial mm sums (4 MB)
__device__ float g_sb[BATCH];                // per-batch logK - log(sum_j t)
__device__ unsigned int g_q1done[BATCH];     // Q1-slices-done per batch (to 16)
__device__ unsigned int g_bt[BATCH];         // Q0+P1 blocks done per batch (to 32)
__device__ unsigned int g_tickF;             // batches finished (to 128)
// All counters are zero-initialized and reset by their last user each launch.

__device__ __forceinline__ float4 ldcs4(const float4* p) { return __ldcs(p); }

// Streaming column-sum body: 32 rows x 512 cols, 4 float4 in flight.
__device__ __forceinline__ void colsum_body(const float* __restrict__ src,
                                            float* __restrict__ dst,
                                            int b, int slice, int t)
{
    const float4* p = (const float4*)(src + (size_t)b * KK * KK
                                          + (size_t)(slice * SLRQ) * KK) + t;
    const int rs = KK / 4;

    float sx = 0.f, sy = 0.f, sz = 0.f, sw = 0.f;
#pragma unroll
    for (int i = 0; i < SLRQ; i += 4) {
        float4 a0 = ldcs4(p + (i + 0) * rs);
        float4 a1 = ldcs4(p + (i + 1) * rs);
        float4 a2 = ldcs4(p + (i + 2) * rs);
        float4 a3 = ldcs4(p + (i + 3) * rs);
        sx += __expf(a0.x) + __expf(a1.x) + __expf(a2.x) + __expf(a3.x);
        sy += __expf(a0.y) + __expf(a1.y) + __expf(a2.y) + __expf(a3.y);
        sz += __expf(a0.z) + __expf(a1.z) + __expf(a2.z) + __expf(a3.z);
        sw += __expf(a0.w) + __expf(a1.w) + __expf(a2.w) + __expf(a3.w);
    }
    ((float4*)(dst + ((size_t)slice * BATCH + b) * KK))[t] =
        make_float4(sx, sy, sz, sw);
}

// ---------------------------------------------------------------------------
// Mega-kernel: 1D grid of 6144 blocks, 128 threads.
//   bid [0,2048)    : Q1 colsum  (E1 partials) -> release g_q1done[b]
//   bid [2048,4096) : Q0 colsum  (E0 partials) -> tick g_bt[b]
//   bid [4096,6144) : P1 mid     (spin on g_q1done[b], build ew, mmp partial)
//                     -> tick g_bt[b]; last of 32 finishes batch; global
//                     ticket does the deterministic batch tree-sum -> out.
// Wave 1 = bids 0..~2071 (all Q1) -> E1 done before any P1 block is resident,
// so spins are ~free. One launch: continuous 402 MB stream, no launch gaps.
// ---------------------------------------------------------------------------
__global__ void __launch_bounds__(TPB, 14) k_mega(const float* __restrict__ Q0,
                                                  const float* __restrict__ Q1,
                                                  const float* __restrict__ P0,
                                                  const float* __restrict__ P1,
                                                  const float* __restrict__ P2,
                                                  float* __restrict__ out)
{
    const int bid = blockIdx.x;
    const int t   = threadIdx.x;

    if (bid < 2048) {
        // ---------------- Q1 colsum ----------------
        const int slice = bid & 15;
        const int b     = bid >> 4;
        colsum_body(Q1, g_Ep1, b, slice, t);
        __threadfence();                         // release partials
        __syncthreads();
        if (t == 0) atomicAdd(&g_q1done[b], 1u);
        return;
    }

    bool lastOfBatch = false;
    int b;

    if (bid < 4096) {
        // ---------------- Q0 colsum ----------------
        const int idx   = bid - 2048;
        const int slice = idx & 15;
        b = idx >> 4;
        colsum_body(Q0, g_Ep0, b, slice, t);
        __threadfence();
        __syncthreads();
        __shared__ bool lastSh;
        if (t == 0) lastSh = (atomicAdd(&g_bt[b], 1u) == 2 * NSLQ - 1);
        __syncthreads();
        lastOfBatch = lastSh;
    } else {
        // ---------------- P1 mid ----------------
        const int idx   = bid - 4096;
        const int slice = idx & 15;
        b = idx >> 4;
        const int i0 = slice * SLRQ;

        // Wait until all 16 Q1 slices of batch b are stored (usually already).
        if (t == 0) {
            while (*(volatile unsigned int*)&g_q1done[b] < NSLQ)
                __nanosleep(64);
        }
        __syncthreads();
        __threadfence();                         // acquire partials

        __shared__ float ew[SLRQ];
        if (t < SLRQ) {
            const int i = i0 + t;
            float e1 = 0.f;
#pragma unroll
            for (int s = 0; s < NSLQ; s++)
                e1 += g_Ep1[((size_t)s * BATCH + b) * KK + i];
            ew[t] = __expf(P0[b * KK + i]) * (float)KK / e1;
        }
        __syncthreads();

        const float4* p = (const float4*)(P1 + (size_t)b * KK * KK
                                             + (size_t)i0 * KK) + t;
        const int rs = KK / 4;

        float sx = 0.f, sy = 0.f, sz = 0.f, sw = 0.f;
#pragma unroll
        for (int i = 0; i < SLRQ; i += 4) {
            float4 a0 = ldcs4(p + (i + 0) * rs);
            float4 a1 = ldcs4(p + (i + 1) * rs);
            float4 a2 = ldcs4(p + (i + 2) * rs);
            float4 a3 = ldcs4(p + (i + 3) * rs);
            float w0 = ew[i + 0], w1 = ew[i + 1], w2 = ew[i + 2], w3 = ew[i + 3];
            sx += w0 * __expf(a0.x) + w1 * __expf(a1.x)
                + w2 * __expf(a2.x) + w3 * __expf(a3.x);
            sy += w0 * __expf(a0.y) + w1 * __expf(a1.y)
                + w2 * __expf(a2.y) + w3 * __expf(a3.y);
            sz += w0 * __expf(a0.z) + w1 * __expf(a1.z)
                + w2 * __expf(a2.z) + w3 * __expf(a3.z);
            sw += w0 * __expf(a0.w) + w1 * __expf(a1.w)
                + w2 * __expf(a2.w) + w3 * __expf(a3.w);
        }
        ((float4*)(g_mmp + ((size_t)slice * BATCH + b) * KK))[t] =
            make_float4(sx, sy, sz, sw);

        __threadfence();
        __syncthreads();
        __shared__ bool lastSh;
        if (t == 0) lastSh = (atomicAdd(&g_bt[b], 1u) == 2 * NSLQ - 1);
        __syncthreads();
        lastOfBatch = lastSh;
    }

    // ------------- per-batch finish (last of 32 Q0+P1 blocks) -------------
    if (lastOfBatch) {
        __threadfence();   // acquire all partials of batch b

        float acc = 0.f;
#pragma unroll
        for (int c = 0; c < 4; c++) {
            const int j = c * TPB + t;
            float m = 0.f, e0 = 0.f;
#pragma unroll
            for (int s = 0; s < NSLQ; s++) {
                m  += g_mmp[((size_t)s * BATCH + b) * KK + j];
                e0 += g_Ep0[((size_t)s * BATCH + b) * KK + j];
            }
            acc += m / e0 * __expf(P2[b * KK + j]);
        }
#pragma unroll
        for (int o = 16; o; o >>= 1)
            acc += __shfl_down_sync(0xFFFFFFFFu, acc, o);

        __shared__ float red[4];
        if ((t & 31) == 0) red[t >> 5] = acc;
        __syncthreads();

        __shared__ bool amFinal;
        if (t == 0) {
            float r = (red[0] + red[1]) + (red[2] + red[3]);
            g_sb[b] = LOGK - logf(r);
            g_bt[b]     = 0;       // reset per-batch counters for replay
            g_q1done[b] = 0;
            __threadfence();
            amFinal = (atomicAdd(&g_tickF, 1u) == BATCH - 1);
        }
        __syncthreads();

        if (amFinal) {
            // one block: fixed-order tree sum over batches -> deterministic
            __shared__ float sm[BATCH];
            sm[t] = g_sb[t];
            __syncthreads();
#pragma unroll
            for (int off = BATCH / 2; off > 0; off >>= 1) {
                if (t < off) sm[t] += sm[t + off];
                __syncthreads();
            }
            if (t == 0) {
                out[0] = sm[0];
                g_tickF = 0;       // reset for graph replay
            }
        }
    }
}

// ---------------------------------------------------------------------------
extern "C" void kernel_launch(void* const* d_in, const int* in_sizes, int n_in,
                              void* d_out, int out_size)
{
    const float* Q0 = (const float*)d_in[0];  // logQ0 [B,K,K]
    const float* Q1 = (const float*)d_in[1];  // logQ1 [B,K,K]
    const float* P0 = (const float*)d_in[2];  // logP0 [B,1,K]
    const float* P1 = (const float*)d_in[3];  // logP1 [B,K,K]
    const float* P2 = (const float*)d_in[4];  // logP2 [B,K,1]

    k_mega<<<3 * NSLQ * BATCH, TPB>>>(Q0, Q1, P0, P1, P2, (float*)d_out);
}